// round 15
// baseline (speedup 1.0000x reference)
#include <cuda_runtime.h>
#include <cuda_fp16.h>
#include <math.h>
#include <stdint.h>

// Problem dims (fixed)
#define BSZ 4096
#define HD  2048
#define ID  2048
#define NS  3
#define LN_EPS 1e-5f

// GEMM tile config (fp16 mma.sync m16n8k16)
#define BM 128
#define BN 128
#define BK 64                    // f16 elems per K tile (128B rows)
#define NTHREADS 256             // 8 warps, 2x4 grid, warp tile 64x32
#define NSTAGE 3
#define ROWB 144                 // padded row bytes (128 data + 16 pad)
#define STAGE_B (128 * ROWB)     // 18432 bytes per operand stage
#define SMEM_BYTES (NSTAGE * 2 * STAGE_B)  // 110592

// Persistent-kernel work layout
#define N_SUB_TILES 1536         // 32 mb * 48 (s,nb)   -- mb-major order
#define N_FUS_TILES 512          // 32 mb * 16 nb
#define N_LN_TILES  512          // 32 mb * 16 row-groups (8 rows each)
#define N_TILES     (N_SUB_TILES + N_FUS_TILES + N_LN_TILES)
#define MEGA_GRID   296          // 2 CTAs per SM * 148 SMs

// Merged prologue kernel split
#define CVT_BLOCKS 3072
#define PRO_BLOCKS (CVT_BLOCKS + BSZ)   // 7168

// Scratch (static device globals; no dynamic alloc allowed)
__device__ __half g_x16[(size_t)BSZ * ID];
__device__ __half g_sub16[(size_t)NS * BSZ * HD];
__device__ __half g_wih16[(size_t)NS * HD * ID];
__device__ __half g_whh16[(size_t)NS * HD * HD];
__device__ __half g_fw16[(size_t)HD * HD];
__device__ __half g_weighted16[(size_t)BSZ * HD];
__device__ int    g_sel[BSZ];
__device__ unsigned g_work;
__device__ unsigned g_fus_ready[32];
__device__ unsigned g_ln_ready[32];

// ---------------------------------------------------------------------------
// helpers
// ---------------------------------------------------------------------------
__device__ __forceinline__ uint32_t smem_u32(const void* p) {
    uint32_t a;
    asm("{ .reg .u64 t; cvta.to.shared.u64 t, %1; cvt.u32.u64 %0, t; }"
        : "=r"(a) : "l"(p));
    return a;
}
__device__ __forceinline__ void cp16(uint32_t dst, const void* src) {
    asm volatile("cp.async.cg.shared.global [%0], [%1], 16;"
                 :: "r"(dst), "l"(src) : "memory");
}
__device__ __forceinline__ void cp_commit() {
    asm volatile("cp.async.commit_group;" ::: "memory");
}
template <int N> __device__ __forceinline__ void cp_wait() {
    asm volatile("cp.async.wait_group %0;" :: "n"(N) : "memory");
}
__device__ __forceinline__ void ldsm_x4(uint32_t& r0, uint32_t& r1,
                                        uint32_t& r2, uint32_t& r3,
                                        uint32_t addr) {
    asm volatile("ldmatrix.sync.aligned.m8n8.x4.shared.b16 {%0,%1,%2,%3}, [%4];"
                 : "=r"(r0), "=r"(r1), "=r"(r2), "=r"(r3) : "r"(addr));
}
__device__ __forceinline__ void mma_f16(float c[4], uint32_t a0, uint32_t a1,
                                        uint32_t a2, uint32_t a3,
                                        uint32_t b0, uint32_t b1) {
    asm volatile(
        "mma.sync.aligned.m16n8k16.row.col.f32.f16.f16.f32 "
        "{%0,%1,%2,%3}, {%4,%5,%6,%7}, {%8,%9}, {%0,%1,%2,%3};"
        : "+f"(c[0]), "+f"(c[1]), "+f"(c[2]), "+f"(c[3])
        : "r"(a0), "r"(a1), "r"(a2), "r"(a3), "r"(b0), "r"(b1));
}

// ---------------------------------------------------------------------------
// Kernel 0 (merged prologue): blocks [0,CVT_BLOCKS) do f32->f16 conversion;
// blocks [CVT_BLOCKS, PRO_BLOCKS) do gate logits + hard gumbel-softmax.
// ---------------------------------------------------------------------------
#define CVT_C0 1048576ull   // x
#define CVT_C1 4194304ull   // + prev_sub
#define CVT_C2 5767168ull   // + W_ih
#define CVT_C3 7340032ull   // + W_hh
#define CVT_CT 7864320ull   // + fusion_W

__device__ __forceinline__ void cvt_chunk(size_t c,
                                          const float* __restrict__ x,
                                          const float* __restrict__ sub,
                                          const float* __restrict__ wih,
                                          const float* __restrict__ whh,
                                          const float* __restrict__ fw)
{
    const float* in; __half* out; size_t off;
    if (c < CVT_C0)      { in = x;   out = g_x16;   off = c; }
    else if (c < CVT_C1) { in = sub; out = g_sub16; off = c - CVT_C0; }
    else if (c < CVT_C2) { in = wih; out = g_wih16; off = c - CVT_C1; }
    else if (c < CVT_C3) { in = whh; out = g_whh16; off = c - CVT_C2; }
    else                 { in = fw;  out = g_fw16;  off = c - CVT_C3; }
    size_t i = off * 8;
    float4 v0 = *(const float4*)(in + i);
    float4 v1 = *(const float4*)(in + i + 4);
    __half2 h0 = __floats2half2_rn(v0.x, v0.y);
    __half2 h1 = __floats2half2_rn(v0.z, v0.w);
    __half2 h2 = __floats2half2_rn(v1.x, v1.y);
    __half2 h3 = __floats2half2_rn(v1.z, v1.w);
    uint4 o;
    o.x = *(uint32_t*)&h0; o.y = *(uint32_t*)&h1;
    o.z = *(uint32_t*)&h2; o.w = *(uint32_t*)&h3;
    *(uint4*)(out + i) = o;
}

__global__ void prologue_kernel(const float* __restrict__ x,
                                const float* __restrict__ sub,
                                const float* __restrict__ wih,
                                const float* __restrict__ whh,
                                const float* __restrict__ fw,
                                const float* __restrict__ prev_master,
                                const float* __restrict__ gumbel,
                                const float* __restrict__ gate_W,
                                const float* __restrict__ gate_b,
                                float* __restrict__ out_gate)
{
    int blk = blockIdx.x;
    int tid = threadIdx.x;   // 256 threads

    if (blk < CVT_BLOCKS) {
        size_t t0 = (size_t)blk * blockDim.x + tid;
        size_t S  = (size_t)CVT_BLOCKS * blockDim.x;
        for (size_t c = t0; c < CVT_CT; c += 4 * S) {
            cvt_chunk(c, x, sub, wih, whh, fw);
            if (c + S < CVT_CT)     cvt_chunk(c + S, x, sub, wih, whh, fw);
            if (c + 2 * S < CVT_CT) cvt_chunk(c + 2 * S, x, sub, wih, whh, fw);
            if (c + 3 * S < CVT_CT) cvt_chunk(c + 3 * S, x, sub, wih, whh, fw);
        }
        return;
    }

    // ---------------- gate path (one batch row per block) ----------------
    int b = blk - CVT_BLOCKS;

    if (b == 0) {            // reset persistent-kernel counters (every launch)
        if (tid == 0) g_work = 0;
        if (tid < 32) { g_fus_ready[tid] = 0; g_ln_ready[tid] = 0; }
    }

    const float* row = prev_master + (size_t)b * HD;
    float p0 = 0.f, p1 = 0.f, p2 = 0.f;
    for (int h = tid * 4; h < HD; h += 256 * 4) {
        float4 v  = *(const float4*)(row + h);
        float4 w0 = *(const float4*)(gate_W + 0 * HD + h);
        float4 w1 = *(const float4*)(gate_W + 1 * HD + h);
        float4 w2 = *(const float4*)(gate_W + 2 * HD + h);
        p0 += v.x * w0.x + v.y * w0.y + v.z * w0.z + v.w * w0.w;
        p1 += v.x * w1.x + v.y * w1.y + v.z * w1.z + v.w * w1.w;
        p2 += v.x * w2.x + v.y * w2.y + v.z * w2.z + v.w * w2.w;
    }
    #pragma unroll
    for (int o = 16; o > 0; o >>= 1) {
        p0 += __shfl_down_sync(0xffffffffu, p0, o);
        p1 += __shfl_down_sync(0xffffffffu, p1, o);
        p2 += __shfl_down_sync(0xffffffffu, p2, o);
    }
    __shared__ float s0[8], s1[8], s2[8];
    int wid = tid >> 5, lid = tid & 31;
    if (lid == 0) { s0[wid] = p0; s1[wid] = p1; s2[wid] = p2; }
    __syncthreads();
    if (tid == 0) {
        float z0 = gate_b[0] + gumbel[b * 3 + 0];
        float z1 = gate_b[1] + gumbel[b * 3 + 1];
        float z2 = gate_b[2] + gumbel[b * 3 + 2];
        #pragma unroll
        for (int w = 0; w < 8; w++) { z0 += s0[w]; z1 += s1[w]; z2 += s2[w]; }
        int am = 0; float zm = z0;
        if (z1 > zm) { am = 1; zm = z1; }
        if (z2 > zm) { am = 2; }
        out_gate[b * 3 + 0] = (am == 0) ? 1.f : 0.f;
        out_gate[b * 3 + 1] = (am == 1) ? 1.f : 0.f;
        out_gate[b * 3 + 2] = (am == 2) ? 1.f : 0.f;
        g_sel[b] = am;
    }
}

// ---------------------------------------------------------------------------
// fp16 mma.sync GEMM core.  C[128,128] per CTA, 8 warps 2x4, warp tile 64x32.
// ---------------------------------------------------------------------------
struct GemmCtx {
    uint32_t sm32;
    int tid, lane, g, tg, wm0, wn0;
};

__device__ __forceinline__ void gemm_init(GemmCtx& cx, void* sm) {
    cx.sm32 = smem_u32(sm);
    cx.tid  = threadIdx.x;
    cx.lane = cx.tid & 31;
    cx.g    = cx.lane >> 2;
    cx.tg   = cx.lane & 3;
    int wid = cx.tid >> 5;
    cx.wm0  = (wid >> 2) * 64;   // 2 warp-rows
    cx.wn0  = (wid & 3) * 32;    // 4 warp-cols
}

// load one BK=64 tile of A (rows m0..+127) and B (rows n0..+127) into stage sl
__device__ __forceinline__ void gemm_load(const GemmCtx& cx,
                                          const __half* __restrict__ A, int m0,
                                          const __half* __restrict__ Bw, int n0,
                                          int kc, int sl) {
    int r0  = cx.tid >> 3;         // 0..31
    int seg = cx.tid & 7;          // 16B segment in row
    uint32_t abase = cx.sm32 + sl * (2 * STAGE_B);
    uint32_t bbase = abase + STAGE_B;
    #pragma unroll
    for (int p = 0; p < 4; p++) {
        int r = r0 + p * 32;
        cp16(abase + r * ROWB + seg * 16, A  + (size_t)(m0 + r) * 2048 + kc + seg * 8);
        cp16(bbase + r * ROWB + seg * 16, Bw + (size_t)(n0 + r) * 2048 + kc + seg * 8);
    }
}

__device__ __forceinline__ void gemm_compute(const GemmCtx& cx, int sl,
                                             float c[4][4][4]) {
    uint32_t As = cx.sm32 + sl * (2 * STAGE_B);
    uint32_t Bs = As + STAGE_B;
    int l = cx.lane;
    int arow = cx.wm0 + (l & 15);
    int aks  = (l >> 4) * 8;
    int brow0 = cx.wn0 + (l & 7) + ((l >> 4) << 3);
    int bks  = ((l >> 3) & 1) * 8;
    #pragma unroll
    for (int kk = 0; kk < BK; kk += 16) {
        uint32_t a[4][4], b[4][2];
        #pragma unroll
        for (int i = 0; i < 4; i++) {
            ldsm_x4(a[i][0], a[i][1], a[i][2], a[i][3],
                    As + (arow + i * 16) * ROWB + (kk + aks) * 2);
        }
        #pragma unroll
        for (int j2 = 0; j2 < 2; j2++) {
            ldsm_x4(b[j2 * 2][0], b[j2 * 2][1], b[j2 * 2 + 1][0], b[j2 * 2 + 1][1],
                    Bs + (brow0 + j2 * 16) * ROWB + (kk + bks) * 2);
        }
        #pragma unroll
        for (int i = 0; i < 4; i++)
            #pragma unroll
            for (int j = 0; j < 4; j++)
                mma_f16(c[i][j], a[i][0], a[i][1], a[i][2], a[i][3],
                        b[j][0], b[j][1]);
    }
}

// Full K-loop GEMM: operands (A0,B0) for tiles [0,split), (A1,B1) after.
__device__ __forceinline__ void gemm_run(const GemmCtx& cx,
                                         const __half* A0, const __half* B0,
                                         const __half* A1, const __half* B1,
                                         int m0, int n0, int NT, int split,
                                         float c[4][4][4])
{
    #pragma unroll
    for (int i = 0; i < 4; i++)
        #pragma unroll
        for (int j = 0; j < 4; j++)
            #pragma unroll
            for (int q = 0; q < 4; q++) c[i][j][q] = 0.f;

    auto tl = [&](int t, int sl) {
        const __half* A; const __half* B; int kc;
        if (t < split) { A = A0; B = B0; kc = t * BK; }
        else           { A = A1; B = B1; kc = (t - split) * BK; }
        gemm_load(cx, A, m0, B, n0, kc, sl);
    };

    tl(0, 0); cp_commit();
    tl(1, 1); cp_commit();

    for (int t = 0; t < NT; t++) {
        cp_wait<NSTAGE - 2>();
        __syncthreads();
        int nt = t + NSTAGE - 1;
        if (nt < NT) tl(nt, nt % NSTAGE);
        cp_commit();
        gemm_compute(cx, t % NSTAGE, c);
    }
    cp_wait<0>();
    __syncthreads();
}

// spin until *p >= tgt (one thread polls, then CTA-wide acquire)
__device__ __forceinline__ void wait_count(volatile unsigned* p, unsigned tgt) {
    if (threadIdx.x == 0) {
        while (*p < tgt) __nanosleep(64);
    }
    __syncthreads();
    __threadfence();
}

// ---------------------------------------------------------------------------
// Kernel 1 (persistent mega): subcell tiles (mb-major) -> fusion -> LN
// ---------------------------------------------------------------------------
__global__ __launch_bounds__(NTHREADS, 2)
void mega_kernel(const float* __restrict__ b_ih,
                 const float* __restrict__ b_hh,
                 const float* __restrict__ fusion_b,
                 const float* __restrict__ prev_master,
                 const float* __restrict__ ln_g,
                 const float* __restrict__ ln_b,
                 float* __restrict__ out_sub,
                 float* __restrict__ out_master)
{
    extern __shared__ char smraw[];
    GemmCtx cx; gemm_init(cx, smraw);
    __shared__ unsigned sw;
    float c[4][4][4];

    for (;;) {
        __syncthreads();
        if (threadIdx.x == 0) sw = atomicAdd(&g_work, 1u);
        __syncthreads();
        unsigned w = sw;
        if (w >= N_TILES) return;

        if (w < N_SUB_TILES) {
            // ---------------- subcell tile (mb-major order) ----------------
            int mb = w / 48;
            int r  = w % 48;
            int s  = r / 16;
            int nb = r % 16;
            int m0 = mb * BM, n0 = nb * BN;

            // prefetch gather selectors for this tile's rows (ready pre-launch)
            int sel_pre[4][2];
            #pragma unroll
            for (int i = 0; i < 4; i++) {
                int rlo = m0 + cx.wm0 + i * 16 + cx.g;
                sel_pre[i][0] = __ldg(&g_sel[rlo]);
                sel_pre[i][1] = __ldg(&g_sel[rlo + 8]);
            }

            gemm_run(cx, g_x16, g_wih16 + (size_t)s * HD * ID,
                     g_sub16 + (size_t)s * BSZ * HD,
                     g_whh16 + (size_t)s * HD * HD,
                     m0, n0, 64, 32, c);

            const float* bi = b_ih + (size_t)s * HD;
            const float* bh = b_hh + (size_t)s * HD;
            #pragma unroll
            for (int i = 0; i < 4; i++) {
                int rlo = m0 + cx.wm0 + i * 16 + cx.g;
                int rhi = rlo + 8;
                int selo = sel_pre[i][0], sehi = sel_pre[i][1];
                float* olo = out_sub + ((size_t)s * BSZ + rlo) * HD;
                float* ohi = out_sub + ((size_t)s * BSZ + rhi) * HD;
                __half* wlo = g_weighted16 + (size_t)rlo * HD;
                __half* whi = g_weighted16 + (size_t)rhi * HD;
                #pragma unroll
                for (int j = 0; j < 4; j++) {
                    int n = n0 + cx.wn0 + j * 8 + cx.tg * 2;
                    float2 bv0 = *(const float2*)(bi + n);
                    float2 bv1 = *(const float2*)(bh + n);
                    float bs0 = bv0.x + bv1.x, bs1 = bv0.y + bv1.y;
                    float2 vlo = make_float2(tanhf(c[i][j][0] + bs0),
                                             tanhf(c[i][j][1] + bs1));
                    float2 vhi = make_float2(tanhf(c[i][j][2] + bs0),
                                             tanhf(c[i][j][3] + bs1));
                    *(float2*)(olo + n) = vlo;
                    *(float2*)(ohi + n) = vhi;
                    if (selo == s) *(__half2*)(wlo + n) = __floats2half2_rn(vlo.x, vlo.y);
                    if (sehi == s) *(__half2*)(whi + n) = __floats2half2_rn(vhi.x, vhi.y);
                }
            }
            __threadfence();
            __syncthreads();
            if (threadIdx.x == 0) atomicAdd(&g_fus_ready[mb], 1u);

        } else if (w < N_SUB_TILES + N_FUS_TILES) {
            // ---------------- fusion tile ----------------
            int f  = w - N_SUB_TILES;
            int mb = f / 16;
            int nb = f % 16;
            int m0 = mb * BM, n0 = nb * BN;

            wait_count(&g_fus_ready[mb], 48u);   // 3 s * 16 nb subcell tiles

            gemm_run(cx, g_weighted16, g_fw16, g_weighted16, g_fw16,
                     m0, n0, 32, 32, c);

            #pragma unroll
            for (int i = 0; i < 4; i++) {
                int rlo = m0 + cx.wm0 + i * 16 + cx.g;
                int rhi = rlo + 8;
                const float* plo = prev_master + (size_t)rlo * HD;
                const float* phi = prev_master + (size_t)rhi * HD;
                float* olo = out_master + (size_t)rlo * HD;
                float* ohi = out_master + (size_t)rhi * HD;
                #pragma unroll
                for (int j = 0; j < 4; j++) {
                    int n = n0 + cx.wn0 + j * 8 + cx.tg * 2;
                    float2 fb = *(const float2*)(fusion_b + n);
                    float2 mlo = *(const float2*)(plo + n);
                    float2 mhi = *(const float2*)(phi + n);
                    float2 vlo = make_float2(c[i][j][0] + fb.x + mlo.x,
                                             c[i][j][1] + fb.y + mlo.y);
                    float2 vhi = make_float2(c[i][j][2] + fb.x + mhi.x,
                                             c[i][j][3] + fb.y + mhi.y);
                    *(float2*)(olo + n) = vlo;
                    *(float2*)(ohi + n) = vhi;
                }
            }
            __threadfence();
            __syncthreads();
            if (threadIdx.x == 0) atomicAdd(&g_ln_ready[mb], 1u);

        } else {
            // -------- LayerNorm + sigmoid tile (8 rows; 1 row per warp) --------
            int idx = w - (N_SUB_TILES + N_FUS_TILES);
            int mb  = idx / 16;
            int grp = idx % 16;
            wait_count(&g_ln_ready[mb], 16u);    // all 16 fusion nb tiles

            int wid = cx.tid >> 5, lid = cx.lane;
            int rowi = mb * 128 + grp * 8 + wid;
            float* row = out_master + (size_t)rowi * HD;
            float sum = 0.f, sq = 0.f;
            #pragma unroll 4
            for (int h = lid * 4; h < HD; h += 128) {
                float4 t = *(const float4*)(row + h);
                sum += t.x + t.y + t.z + t.w;
                sq  += t.x * t.x + t.y * t.y + t.z * t.z + t.w * t.w;
            }
            #pragma unroll
            for (int o = 16; o > 0; o >>= 1) {
                sum += __shfl_xor_sync(0xffffffffu, sum, o);
                sq  += __shfl_xor_sync(0xffffffffu, sq, o);
            }
            float mu   = sum / (float)HD;
            float var  = sq / (float)HD - mu * mu;
            float rstd = rsqrtf(var + LN_EPS);
            #pragma unroll 4
            for (int h = lid * 4; h < HD; h += 128) {
                float4 t = *(const float4*)(row + h);
                float4 gg = *(const float4*)(ln_g + h);
                float4 bb = *(const float4*)(ln_b + h);
                float n0v = (t.x - mu) * rstd * gg.x + bb.x;
                float n1v = (t.y - mu) * rstd * gg.y + bb.y;
                float n2v = (t.z - mu) * rstd * gg.z + bb.z;
                float n3v = (t.w - mu) * rstd * gg.w + bb.w;
                float4 o;
                o.x = 1.f / (1.f + expf(-n0v));
                o.y = 1.f / (1.f + expf(-n1v));
                o.z = 1.f / (1.f + expf(-n2v));
                o.w = 1.f / (1.f + expf(-n3v));
                *(float4*)(row + h) = o;
            }
        }
    }
}

// ---------------------------------------------------------------------------
// Launch
// ---------------------------------------------------------------------------
extern "C" void kernel_launch(void* const* d_in, const int* in_sizes, int n_in,
                              void* d_out, int out_size)
{
    const float* x           = (const float*)d_in[0];   // [B, I]
    const float* prev_master = (const float*)d_in[1];   // [B, H]
    const float* prev_sub    = (const float*)d_in[2];   // [S, B, H]
    const float* gumbel      = (const float*)d_in[3];   // [B, S]
    const float* W_ih        = (const float*)d_in[4];   // [S, H, I]
    const float* W_hh        = (const float*)d_in[5];   // [S, H, H]
    const float* b_ih        = (const float*)d_in[6];   // [S, H]
    const float* b_hh        = (const float*)d_in[7];   // [S, H]
    const float* gate_W      = (const float*)d_in[8];   // [S, H]
    const float* gate_b      = (const float*)d_in[9];   // [S]
    const float* fusion_W    = (const float*)d_in[10];  // [H, H]
    const float* fusion_b    = (const float*)d_in[11];  // [H]
    const float* ln_g        = (const float*)d_in[12];  // [H]
    const float* ln_b        = (const float*)d_in[13];  // [H]

    float* out        = (float*)d_out;
    float* out_master = out;                                  // B*H
    float* out_gate   = out + (size_t)BSZ * HD;               // B*S
    float* out_sub    = out + (size_t)BSZ * HD + BSZ * NS;    // S*B*H

    cudaFuncSetAttribute(mega_kernel,
                         cudaFuncAttributeMaxDynamicSharedMemorySize, SMEM_BYTES);

    prologue_kernel<<<PRO_BLOCKS, 256>>>(x, prev_sub, W_ih, W_hh, fusion_W,
                                         prev_master, gumbel, gate_W, gate_b,
                                         out_gate);

    mega_kernel<<<MEGA_GRID, NTHREADS, SMEM_BYTES>>>(
        b_ih, b_hh, fusion_b, prev_master, ln_g, ln_b, out_sub, out_master);
}

// round 16
// speedup vs baseline: 1.5005x; 1.5005x over previous
#include <cuda_runtime.h>
#include <cuda_fp16.h>
#include <math.h>
#include <stdint.h>

// Problem dims (fixed)
#define BSZ 4096
#define HD  2048
#define ID  2048
#define NS  3
#define LN_EPS 1e-5f

// GEMM tile config (fp16 mma.sync m16n8k16)
#define BM 128
#define BN 128
#define BK 64                    // f16 elems per K tile (128B rows)
#define NTHREADS 256             // 8 warps, 2x4 grid, warp tile 64x32
#define NSTAGE 3
#define ROWB 144                 // padded row bytes (128 data + 16 pad)
#define STAGE_B (128 * ROWB)     // 18432 bytes per operand stage
#define SMEM_BYTES (NSTAGE * 2 * STAGE_B)  // 110592

// Persistent-kernel work layout
#define N_SUB_TILES 1536         // 32 mb * 48 (s,nb)   -- mb-major order
#define N_FUS_TILES 512          // 32 mb * 16 nb
#define N_LN_TILES  512          // 32 mb * 16 row-groups (8 rows each)
#define N_TILES     (N_SUB_TILES + N_FUS_TILES + N_LN_TILES)
#define MEGA_GRID   296          // 2 CTAs per SM * 148 SMs

// Merged prologue kernel split
#define CVT_BLOCKS 3072
#define PRO_BLOCKS (CVT_BLOCKS + BSZ)   // 7168

// Scratch (static device globals; no dynamic alloc allowed)
__device__ __half g_x16[(size_t)BSZ * ID];
__device__ __half g_sub16[(size_t)NS * BSZ * HD];
__device__ __half g_wih16[(size_t)NS * HD * ID];
__device__ __half g_whh16[(size_t)NS * HD * HD];
__device__ __half g_fw16[(size_t)HD * HD];
__device__ __half g_weighted16[(size_t)BSZ * HD];
__device__ int    g_sel[BSZ];
__device__ unsigned g_work;
__device__ unsigned g_fus_ready[32];
__device__ unsigned g_ln_ready[32];

// ---------------------------------------------------------------------------
// helpers
// ---------------------------------------------------------------------------
__device__ __forceinline__ uint32_t smem_u32(const void* p) {
    uint32_t a;
    asm("{ .reg .u64 t; cvta.to.shared.u64 t, %1; cvt.u32.u64 %0, t; }"
        : "=r"(a) : "l"(p));
    return a;
}
__device__ __forceinline__ void cp16(uint32_t dst, const void* src) {
    asm volatile("cp.async.cg.shared.global [%0], [%1], 16;"
                 :: "r"(dst), "l"(src) : "memory");
}
__device__ __forceinline__ void cp_commit() {
    asm volatile("cp.async.commit_group;" ::: "memory");
}
template <int N> __device__ __forceinline__ void cp_wait() {
    asm volatile("cp.async.wait_group %0;" :: "n"(N) : "memory");
}
__device__ __forceinline__ void ldsm_x4(uint32_t& r0, uint32_t& r1,
                                        uint32_t& r2, uint32_t& r3,
                                        uint32_t addr) {
    asm volatile("ldmatrix.sync.aligned.m8n8.x4.shared.b16 {%0,%1,%2,%3}, [%4];"
                 : "=r"(r0), "=r"(r1), "=r"(r2), "=r"(r3) : "r"(addr));
}
__device__ __forceinline__ void mma_f16(float c[4], uint32_t a0, uint32_t a1,
                                        uint32_t a2, uint32_t a3,
                                        uint32_t b0, uint32_t b1) {
    asm volatile(
        "mma.sync.aligned.m16n8k16.row.col.f32.f16.f16.f32 "
        "{%0,%1,%2,%3}, {%4,%5,%6,%7}, {%8,%9}, {%0,%1,%2,%3};"
        : "+f"(c[0]), "+f"(c[1]), "+f"(c[2]), "+f"(c[3])
        : "r"(a0), "r"(a1), "r"(a2), "r"(a3), "r"(b0), "r"(b1));
}

// ---------------------------------------------------------------------------
// Kernel 0 (merged prologue): blocks [0,CVT_BLOCKS) do f32->f16 conversion;
// blocks [CVT_BLOCKS, PRO_BLOCKS) do gate logits + hard gumbel-softmax.
// ---------------------------------------------------------------------------
#define CVT_C0 1048576ull   // x
#define CVT_C1 4194304ull   // + prev_sub
#define CVT_C2 5767168ull   // + W_ih
#define CVT_C3 7340032ull   // + W_hh
#define CVT_CT 7864320ull   // + fusion_W

__device__ __forceinline__ void cvt_chunk(size_t c,
                                          const float* __restrict__ x,
                                          const float* __restrict__ sub,
                                          const float* __restrict__ wih,
                                          const float* __restrict__ whh,
                                          const float* __restrict__ fw)
{
    const float* in; __half* out; size_t off;
    if (c < CVT_C0)      { in = x;   out = g_x16;   off = c; }
    else if (c < CVT_C1) { in = sub; out = g_sub16; off = c - CVT_C0; }
    else if (c < CVT_C2) { in = wih; out = g_wih16; off = c - CVT_C1; }
    else if (c < CVT_C3) { in = whh; out = g_whh16; off = c - CVT_C2; }
    else                 { in = fw;  out = g_fw16;  off = c - CVT_C3; }
    size_t i = off * 8;
    float4 v0 = *(const float4*)(in + i);
    float4 v1 = *(const float4*)(in + i + 4);
    __half2 h0 = __floats2half2_rn(v0.x, v0.y);
    __half2 h1 = __floats2half2_rn(v0.z, v0.w);
    __half2 h2 = __floats2half2_rn(v1.x, v1.y);
    __half2 h3 = __floats2half2_rn(v1.z, v1.w);
    uint4 o;
    o.x = *(uint32_t*)&h0; o.y = *(uint32_t*)&h1;
    o.z = *(uint32_t*)&h2; o.w = *(uint32_t*)&h3;
    *(uint4*)(out + i) = o;
}

__global__ void prologue_kernel(const float* __restrict__ x,
                                const float* __restrict__ sub,
                                const float* __restrict__ wih,
                                const float* __restrict__ whh,
                                const float* __restrict__ fw,
                                const float* __restrict__ prev_master,
                                const float* __restrict__ gumbel,
                                const float* __restrict__ gate_W,
                                const float* __restrict__ gate_b,
                                float* __restrict__ out_gate)
{
    int blk = blockIdx.x;
    int tid = threadIdx.x;   // 256 threads

    if (blk < CVT_BLOCKS) {
        size_t t0 = (size_t)blk * blockDim.x + tid;
        size_t S  = (size_t)CVT_BLOCKS * blockDim.x;
        for (size_t c = t0; c < CVT_CT; c += 4 * S) {
            cvt_chunk(c, x, sub, wih, whh, fw);
            if (c + S < CVT_CT)     cvt_chunk(c + S, x, sub, wih, whh, fw);
            if (c + 2 * S < CVT_CT) cvt_chunk(c + 2 * S, x, sub, wih, whh, fw);
            if (c + 3 * S < CVT_CT) cvt_chunk(c + 3 * S, x, sub, wih, whh, fw);
        }
        return;
    }

    // ---------------- gate path (one batch row per block) ----------------
    int b = blk - CVT_BLOCKS;

    if (b == 0) {            // reset persistent-kernel counters (every launch)
        if (tid == 0) g_work = 0;
        if (tid < 32) { g_fus_ready[tid] = 0; g_ln_ready[tid] = 0; }
    }

    const float* row = prev_master + (size_t)b * HD;
    float p0 = 0.f, p1 = 0.f, p2 = 0.f;
    for (int h = tid * 4; h < HD; h += 256 * 4) {
        float4 v  = *(const float4*)(row + h);
        float4 w0 = *(const float4*)(gate_W + 0 * HD + h);
        float4 w1 = *(const float4*)(gate_W + 1 * HD + h);
        float4 w2 = *(const float4*)(gate_W + 2 * HD + h);
        p0 += v.x * w0.x + v.y * w0.y + v.z * w0.z + v.w * w0.w;
        p1 += v.x * w1.x + v.y * w1.y + v.z * w1.z + v.w * w1.w;
        p2 += v.x * w2.x + v.y * w2.y + v.z * w2.z + v.w * w2.w;
    }
    #pragma unroll
    for (int o = 16; o > 0; o >>= 1) {
        p0 += __shfl_down_sync(0xffffffffu, p0, o);
        p1 += __shfl_down_sync(0xffffffffu, p1, o);
        p2 += __shfl_down_sync(0xffffffffu, p2, o);
    }
    __shared__ float s0[8], s1[8], s2[8];
    int wid = tid >> 5, lid = tid & 31;
    if (lid == 0) { s0[wid] = p0; s1[wid] = p1; s2[wid] = p2; }
    __syncthreads();
    if (tid == 0) {
        float z0 = gate_b[0] + gumbel[b * 3 + 0];
        float z1 = gate_b[1] + gumbel[b * 3 + 1];
        float z2 = gate_b[2] + gumbel[b * 3 + 2];
        #pragma unroll
        for (int w = 0; w < 8; w++) { z0 += s0[w]; z1 += s1[w]; z2 += s2[w]; }
        int am = 0; float zm = z0;
        if (z1 > zm) { am = 1; zm = z1; }
        if (z2 > zm) { am = 2; }
        out_gate[b * 3 + 0] = (am == 0) ? 1.f : 0.f;
        out_gate[b * 3 + 1] = (am == 1) ? 1.f : 0.f;
        out_gate[b * 3 + 2] = (am == 2) ? 1.f : 0.f;
        g_sel[b] = am;
    }
}

// ---------------------------------------------------------------------------
// fp16 mma.sync GEMM core.  C[128,128] per CTA, 8 warps 2x4, warp tile 64x32.
// ---------------------------------------------------------------------------
struct GemmCtx {
    uint32_t sm32;
    int tid, lane, g, tg, wm0, wn0;
};

__device__ __forceinline__ void gemm_init(GemmCtx& cx, void* sm) {
    cx.sm32 = smem_u32(sm);
    cx.tid  = threadIdx.x;
    cx.lane = cx.tid & 31;
    cx.g    = cx.lane >> 2;
    cx.tg   = cx.lane & 3;
    int wid = cx.tid >> 5;
    cx.wm0  = (wid >> 2) * 64;   // 2 warp-rows
    cx.wn0  = (wid & 3) * 32;    // 4 warp-cols
}

// load one BK=64 tile of A (rows m0..+127) and B (rows n0..+127) into stage sl
__device__ __forceinline__ void gemm_load(const GemmCtx& cx,
                                          const __half* __restrict__ A, int m0,
                                          const __half* __restrict__ Bw, int n0,
                                          int kc, int sl) {
    int r0  = cx.tid >> 3;         // 0..31
    int seg = cx.tid & 7;          // 16B segment in row
    uint32_t abase = cx.sm32 + sl * (2 * STAGE_B);
    uint32_t bbase = abase + STAGE_B;
    #pragma unroll
    for (int p = 0; p < 4; p++) {
        int r = r0 + p * 32;
        cp16(abase + r * ROWB + seg * 16, A  + (size_t)(m0 + r) * 2048 + kc + seg * 8);
        cp16(bbase + r * ROWB + seg * 16, Bw + (size_t)(n0 + r) * 2048 + kc + seg * 8);
    }
}

__device__ __forceinline__ void gemm_compute(const GemmCtx& cx, int sl,
                                             float c[4][4][4]) {
    uint32_t As = cx.sm32 + sl * (2 * STAGE_B);
    uint32_t Bs = As + STAGE_B;
    int l = cx.lane;
    int arow = cx.wm0 + (l & 15);
    int aks  = (l >> 4) * 8;
    int brow0 = cx.wn0 + (l & 7) + ((l >> 4) << 3);
    int bks  = ((l >> 3) & 1) * 8;
    #pragma unroll
    for (int kk = 0; kk < BK; kk += 16) {
        uint32_t a[4][4], b[4][2];
        #pragma unroll
        for (int i = 0; i < 4; i++) {
            ldsm_x4(a[i][0], a[i][1], a[i][2], a[i][3],
                    As + (arow + i * 16) * ROWB + (kk + aks) * 2);
        }
        #pragma unroll
        for (int j2 = 0; j2 < 2; j2++) {
            ldsm_x4(b[j2 * 2][0], b[j2 * 2][1], b[j2 * 2 + 1][0], b[j2 * 2 + 1][1],
                    Bs + (brow0 + j2 * 16) * ROWB + (kk + bks) * 2);
        }
        #pragma unroll
        for (int i = 0; i < 4; i++)
            #pragma unroll
            for (int j = 0; j < 4; j++)
                mma_f16(c[i][j], a[i][0], a[i][1], a[i][2], a[i][3],
                        b[j][0], b[j][1]);
    }
}

// Full K-loop GEMM: operands (A0,B0) for tiles [0,split), (A1,B1) after.
__device__ __forceinline__ void gemm_run(const GemmCtx& cx,
                                         const __half* A0, const __half* B0,
                                         const __half* A1, const __half* B1,
                                         int m0, int n0, int NT, int split,
                                         float c[4][4][4])
{
    #pragma unroll
    for (int i = 0; i < 4; i++)
        #pragma unroll
        for (int j = 0; j < 4; j++)
            #pragma unroll
            for (int q = 0; q < 4; q++) c[i][j][q] = 0.f;

    auto tl = [&](int t, int sl) {
        const __half* A; const __half* B; int kc;
        if (t < split) { A = A0; B = B0; kc = t * BK; }
        else           { A = A1; B = B1; kc = (t - split) * BK; }
        gemm_load(cx, A, m0, B, n0, kc, sl);
    };

    tl(0, 0); cp_commit();
    tl(1, 1); cp_commit();

    for (int t = 0; t < NT; t++) {
        cp_wait<NSTAGE - 2>();
        __syncthreads();
        int nt = t + NSTAGE - 1;
        if (nt < NT) tl(nt, nt % NSTAGE);
        cp_commit();
        gemm_compute(cx, t % NSTAGE, c);
    }
    cp_wait<0>();
    __syncthreads();
}

// spin until *p >= tgt (one thread polls, then CTA-wide acquire)
__device__ __forceinline__ void wait_count(volatile unsigned* p, unsigned tgt) {
    if (threadIdx.x == 0) {
        while (*p < tgt) __nanosleep(64);
    }
    __syncthreads();
    __threadfence();
}

// ---------------------------------------------------------------------------
// Kernel 1 (persistent mega): subcell tiles (mb-major) -> fusion -> LN
// ---------------------------------------------------------------------------
__global__ __launch_bounds__(NTHREADS, 2)
void mega_kernel(const float* __restrict__ b_ih,
                 const float* __restrict__ b_hh,
                 const float* __restrict__ fusion_b,
                 const float* __restrict__ prev_master,
                 const float* __restrict__ ln_g,
                 const float* __restrict__ ln_b,
                 float* __restrict__ out_sub,
                 float* __restrict__ out_master)
{
    extern __shared__ char smraw[];
    GemmCtx cx; gemm_init(cx, smraw);
    __shared__ unsigned sw;
    float c[4][4][4];

    for (;;) {
        __syncthreads();
        if (threadIdx.x == 0) sw = atomicAdd(&g_work, 1u);
        __syncthreads();
        unsigned w = sw;
        if (w >= N_TILES) return;

        if (w < N_SUB_TILES) {
            // ---------------- subcell tile (mb-major order) ----------------
            int mb = w / 48;
            int r  = w % 48;
            int s  = r / 16;
            int nb = r % 16;
            int m0 = mb * BM, n0 = nb * BN;

            gemm_run(cx, g_x16, g_wih16 + (size_t)s * HD * ID,
                     g_sub16 + (size_t)s * BSZ * HD,
                     g_whh16 + (size_t)s * HD * HD,
                     m0, n0, 64, 32, c);

            const float* bi = b_ih + (size_t)s * HD;
            const float* bh = b_hh + (size_t)s * HD;
            #pragma unroll
            for (int i = 0; i < 4; i++) {
                int rlo = m0 + cx.wm0 + i * 16 + cx.g;
                int rhi = rlo + 8;
                int selo = g_sel[rlo], sehi = g_sel[rhi];
                float* olo = out_sub + ((size_t)s * BSZ + rlo) * HD;
                float* ohi = out_sub + ((size_t)s * BSZ + rhi) * HD;
                __half* wlo = g_weighted16 + (size_t)rlo * HD;
                __half* whi = g_weighted16 + (size_t)rhi * HD;
                #pragma unroll
                for (int j = 0; j < 4; j++) {
                    int n = n0 + cx.wn0 + j * 8 + cx.tg * 2;
                    float2 bv0 = *(const float2*)(bi + n);
                    float2 bv1 = *(const float2*)(bh + n);
                    float bs0 = bv0.x + bv1.x, bs1 = bv0.y + bv1.y;
                    float2 vlo = make_float2(tanhf(c[i][j][0] + bs0),
                                             tanhf(c[i][j][1] + bs1));
                    float2 vhi = make_float2(tanhf(c[i][j][2] + bs0),
                                             tanhf(c[i][j][3] + bs1));
                    *(float2*)(olo + n) = vlo;
                    *(float2*)(ohi + n) = vhi;
                    if (selo == s) *(__half2*)(wlo + n) = __floats2half2_rn(vlo.x, vlo.y);
                    if (sehi == s) *(__half2*)(whi + n) = __floats2half2_rn(vhi.x, vhi.y);
                }
            }
            __threadfence();
            __syncthreads();
            if (threadIdx.x == 0) atomicAdd(&g_fus_ready[mb], 1u);

        } else if (w < N_SUB_TILES + N_FUS_TILES) {
            // ---------------- fusion tile ----------------
            int f  = w - N_SUB_TILES;
            int mb = f / 16;
            int nb = f % 16;
            int m0 = mb * BM, n0 = nb * BN;

            wait_count(&g_fus_ready[mb], 48u);   // 3 s * 16 nb subcell tiles

            gemm_run(cx, g_weighted16, g_fw16, g_weighted16, g_fw16,
                     m0, n0, 32, 32, c);

            #pragma unroll
            for (int i = 0; i < 4; i++) {
                int rlo = m0 + cx.wm0 + i * 16 + cx.g;
                int rhi = rlo + 8;
                const float* plo = prev_master + (size_t)rlo * HD;
                const float* phi = prev_master + (size_t)rhi * HD;
                float* olo = out_master + (size_t)rlo * HD;
                float* ohi = out_master + (size_t)rhi * HD;
                #pragma unroll
                for (int j = 0; j < 4; j++) {
                    int n = n0 + cx.wn0 + j * 8 + cx.tg * 2;
                    float2 fb = *(const float2*)(fusion_b + n);
                    float2 mlo = *(const float2*)(plo + n);
                    float2 mhi = *(const float2*)(phi + n);
                    float2 vlo = make_float2(c[i][j][0] + fb.x + mlo.x,
                                             c[i][j][1] + fb.y + mlo.y);
                    float2 vhi = make_float2(c[i][j][2] + fb.x + mhi.x,
                                             c[i][j][3] + fb.y + mhi.y);
                    *(float2*)(olo + n) = vlo;
                    *(float2*)(ohi + n) = vhi;
                }
            }
            __threadfence();
            __syncthreads();
            if (threadIdx.x == 0) atomicAdd(&g_ln_ready[mb], 1u);

        } else {
            // -------- LayerNorm + sigmoid tile (8 rows; 1 row per warp) --------
            int idx = w - (N_SUB_TILES + N_FUS_TILES);
            int mb  = idx / 16;
            int grp = idx % 16;
            wait_count(&g_ln_ready[mb], 16u);    // all 16 fusion nb tiles

            int wid = cx.tid >> 5, lid = cx.lane;
            int rowi = mb * 128 + grp * 8 + wid;
            float* row = out_master + (size_t)rowi * HD;
            float sum = 0.f, sq = 0.f;
            #pragma unroll 4
            for (int h = lid * 4; h < HD; h += 128) {
                float4 t = *(const float4*)(row + h);
                sum += t.x + t.y + t.z + t.w;
                sq  += t.x * t.x + t.y * t.y + t.z * t.z + t.w * t.w;
            }
            #pragma unroll
            for (int o = 16; o > 0; o >>= 1) {
                sum += __shfl_xor_sync(0xffffffffu, sum, o);
                sq  += __shfl_xor_sync(0xffffffffu, sq, o);
            }
            float mu   = sum / (float)HD;
            float var  = sq / (float)HD - mu * mu;
            float rstd = rsqrtf(var + LN_EPS);
            #pragma unroll 4
            for (int h = lid * 4; h < HD; h += 128) {
                float4 t = *(const float4*)(row + h);
                float4 gg = *(const float4*)(ln_g + h);
                float4 bb = *(const float4*)(ln_b + h);
                float n0v = (t.x - mu) * rstd * gg.x + bb.x;
                float n1v = (t.y - mu) * rstd * gg.y + bb.y;
                float n2v = (t.z - mu) * rstd * gg.z + bb.z;
                float n3v = (t.w - mu) * rstd * gg.w + bb.w;
                float4 o;
                o.x = 1.f / (1.f + expf(-n0v));
                o.y = 1.f / (1.f + expf(-n1v));
                o.z = 1.f / (1.f + expf(-n2v));
                o.w = 1.f / (1.f + expf(-n3v));
                *(float4*)(row + h) = o;
            }
        }
    }
}

// ---------------------------------------------------------------------------
// Launch
// ---------------------------------------------------------------------------
extern "C" void kernel_launch(void* const* d_in, const int* in_sizes, int n_in,
                              void* d_out, int out_size)
{
    const float* x           = (const float*)d_in[0];   // [B, I]
    const float* prev_master = (const float*)d_in[1];   // [B, H]
    const float* prev_sub    = (const float*)d_in[2];   // [S, B, H]
    const float* gumbel      = (const float*)d_in[3];   // [B, S]
    const float* W_ih        = (const float*)d_in[4];   // [S, H, I]
    const float* W_hh        = (const float*)d_in[5];   // [S, H, H]
    const float* b_ih        = (const float*)d_in[6];   // [S, H]
    const float* b_hh        = (const float*)d_in[7];   // [S, H]
    const float* gate_W      = (const float*)d_in[8];   // [S, H]
    const float* gate_b      = (const float*)d_in[9];   // [S]
    const float* fusion_W    = (const float*)d_in[10];  // [H, H]
    const float* fusion_b    = (const float*)d_in[11];  // [H]
    const float* ln_g        = (const float*)d_in[12];  // [H]
    const float* ln_b        = (const float*)d_in[13];  // [H]

    float* out        = (float*)d_out;
    float* out_master = out;                                  // B*H
    float* out_gate   = out + (size_t)BSZ * HD;               // B*S
    float* out_sub    = out + (size_t)BSZ * HD + BSZ * NS;    // S*B*H

    cudaFuncSetAttribute(mega_kernel,
                         cudaFuncAttributeMaxDynamicSharedMemorySize, SMEM_BYTES);

    prologue_kernel<<<PRO_BLOCKS, 256>>>(x, prev_sub, W_ih, W_hh, fusion_W,
                                         prev_master, gumbel, gate_W, gate_b,
                                         out_gate);

    mega_kernel<<<MEGA_GRID, NTHREADS, SMEM_BYTES>>>(
        b_ih, b_hh, fusion_b, prev_master, ln_g, ln_b, out_sub, out_master);
}

// round 17
// speedup vs baseline: 1.5015x; 1.0006x over previous
#include <cuda_runtime.h>
#include <cuda_fp16.h>
#include <math.h>
#include <stdint.h>

// Problem dims (fixed)
#define BSZ 4096
#define HD  2048
#define ID  2048
#define NS  3
#define LN_EPS 1e-5f

// GEMM tile config (fp16 mma.sync m16n8k16)
#define BM 128
#define BN 128
#define BK 64                    // f16 elems per K tile (128B rows)
#define NTHREADS 256             // 8 warps, 2x4 grid, warp tile 64x32
#define NSTAGE 3
#define ROWB 144                 // padded row bytes (128 data + 16 pad)
#define STAGE_B (128 * ROWB)     // 18432 bytes per operand stage
#define SMEM_BYTES (NSTAGE * 2 * STAGE_B)  // 110592

// Persistent-kernel work layout
#define N_SUB_TILES 1536         // 32 mb * 48 (s,nb)   -- mb-major order
#define N_FUS_TILES 512          // 32 mb * 16 nb
#define N_LN_TILES  512          // 32 mb * 16 row-groups (8 rows each)
#define N_TILES     (N_SUB_TILES + N_FUS_TILES + N_LN_TILES)
#define MEGA_GRID   296          // 2 CTAs per SM * 148 SMs

// Merged prologue kernel split
#define CVT_BLOCKS 3072
#define PRO_BLOCKS (CVT_BLOCKS + BSZ)   // 7168

// Scratch (static device globals; no dynamic alloc allowed)
__device__ __half g_x16[(size_t)BSZ * ID];
__device__ __half g_sub16[(size_t)NS * BSZ * HD];
__device__ __half g_wih16[(size_t)NS * HD * ID];
__device__ __half g_whh16[(size_t)NS * HD * HD];
__device__ __half g_fw16[(size_t)HD * HD];
__device__ __half g_weighted16[(size_t)BSZ * HD];
__device__ int    g_sel[BSZ];
__device__ unsigned g_work;
__device__ unsigned g_fus_ready[32];
__device__ unsigned g_ln_ready[32];

// ---------------------------------------------------------------------------
// helpers
// ---------------------------------------------------------------------------
__device__ __forceinline__ uint32_t smem_u32(const void* p) {
    uint32_t a;
    asm("{ .reg .u64 t; cvta.to.shared.u64 t, %1; cvt.u32.u64 %0, t; }"
        : "=r"(a) : "l"(p));
    return a;
}
__device__ __forceinline__ void cp16(uint32_t dst, const void* src) {
    asm volatile("cp.async.cg.shared.global [%0], [%1], 16;"
                 :: "r"(dst), "l"(src) : "memory");
}
__device__ __forceinline__ void cp_commit() {
    asm volatile("cp.async.commit_group;" ::: "memory");
}
template <int N> __device__ __forceinline__ void cp_wait() {
    asm volatile("cp.async.wait_group %0;" :: "n"(N) : "memory");
}
__device__ __forceinline__ void ldsm_x4(uint32_t& r0, uint32_t& r1,
                                        uint32_t& r2, uint32_t& r3,
                                        uint32_t addr) {
    asm volatile("ldmatrix.sync.aligned.m8n8.x4.shared.b16 {%0,%1,%2,%3}, [%4];"
                 : "=r"(r0), "=r"(r1), "=r"(r2), "=r"(r3) : "r"(addr));
}
__device__ __forceinline__ void mma_f16(float c[4], uint32_t a0, uint32_t a1,
                                        uint32_t a2, uint32_t a3,
                                        uint32_t b0, uint32_t b1) {
    asm volatile(
        "mma.sync.aligned.m16n8k16.row.col.f32.f16.f16.f32 "
        "{%0,%1,%2,%3}, {%4,%5,%6,%7}, {%8,%9}, {%0,%1,%2,%3};"
        : "+f"(c[0]), "+f"(c[1]), "+f"(c[2]), "+f"(c[3])
        : "r"(a0), "r"(a1), "r"(a2), "r"(a3), "r"(b0), "r"(b1));
}

// ---------------------------------------------------------------------------
// Kernel 0 (merged prologue): blocks [0,CVT_BLOCKS) do f32->f16 conversion;
// blocks [CVT_BLOCKS, PRO_BLOCKS) do gate logits + hard gumbel-softmax.
// ---------------------------------------------------------------------------
#define CVT_C0 1048576ull   // x
#define CVT_C1 4194304ull   // + prev_sub
#define CVT_C2 5767168ull   // + W_ih
#define CVT_C3 7340032ull   // + W_hh
#define CVT_CT 7864320ull   // + fusion_W

__device__ __forceinline__ void cvt_chunk(size_t c,
                                          const float* __restrict__ x,
                                          const float* __restrict__ sub,
                                          const float* __restrict__ wih,
                                          const float* __restrict__ whh,
                                          const float* __restrict__ fw)
{
    const float* in; __half* out; size_t off;
    if (c < CVT_C0)      { in = x;   out = g_x16;   off = c; }
    else if (c < CVT_C1) { in = sub; out = g_sub16; off = c - CVT_C0; }
    else if (c < CVT_C2) { in = wih; out = g_wih16; off = c - CVT_C1; }
    else if (c < CVT_C3) { in = whh; out = g_whh16; off = c - CVT_C2; }
    else                 { in = fw;  out = g_fw16;  off = c - CVT_C3; }
    size_t i = off * 8;
    float4 v0 = *(const float4*)(in + i);
    float4 v1 = *(const float4*)(in + i + 4);
    __half2 h0 = __floats2half2_rn(v0.x, v0.y);
    __half2 h1 = __floats2half2_rn(v0.z, v0.w);
    __half2 h2 = __floats2half2_rn(v1.x, v1.y);
    __half2 h3 = __floats2half2_rn(v1.z, v1.w);
    uint4 o;
    o.x = *(uint32_t*)&h0; o.y = *(uint32_t*)&h1;
    o.z = *(uint32_t*)&h2; o.w = *(uint32_t*)&h3;
    *(uint4*)(out + i) = o;
}

__global__ void prologue_kernel(const float* __restrict__ x,
                                const float* __restrict__ sub,
                                const float* __restrict__ wih,
                                const float* __restrict__ whh,
                                const float* __restrict__ fw,
                                const float* __restrict__ prev_master,
                                const float* __restrict__ gumbel,
                                const float* __restrict__ gate_W,
                                const float* __restrict__ gate_b,
                                float* __restrict__ out_gate)
{
    int blk = blockIdx.x;
    int tid = threadIdx.x;   // 256 threads

    if (blk < CVT_BLOCKS) {
        size_t t0 = (size_t)blk * blockDim.x + tid;
        size_t S  = (size_t)CVT_BLOCKS * blockDim.x;
        for (size_t c = t0; c < CVT_CT; c += 4 * S) {
            cvt_chunk(c, x, sub, wih, whh, fw);
            if (c + S < CVT_CT)     cvt_chunk(c + S, x, sub, wih, whh, fw);
            if (c + 2 * S < CVT_CT) cvt_chunk(c + 2 * S, x, sub, wih, whh, fw);
            if (c + 3 * S < CVT_CT) cvt_chunk(c + 3 * S, x, sub, wih, whh, fw);
        }
        return;
    }

    // ---------------- gate path (one batch row per block) ----------------
    int b = blk - CVT_BLOCKS;

    if (b == 0) {            // reset persistent-kernel counters (every launch)
        if (tid == 0) g_work = 0;
        if (tid < 32) { g_fus_ready[tid] = 0; g_ln_ready[tid] = 0; }
    }

    const float* row = prev_master + (size_t)b * HD;
    float p0 = 0.f, p1 = 0.f, p2 = 0.f;
    for (int h = tid * 4; h < HD; h += 256 * 4) {
        float4 v  = *(const float4*)(row + h);
        float4 w0 = *(const float4*)(gate_W + 0 * HD + h);
        float4 w1 = *(const float4*)(gate_W + 1 * HD + h);
        float4 w2 = *(const float4*)(gate_W + 2 * HD + h);
        p0 += v.x * w0.x + v.y * w0.y + v.z * w0.z + v.w * w0.w;
        p1 += v.x * w1.x + v.y * w1.y + v.z * w1.z + v.w * w1.w;
        p2 += v.x * w2.x + v.y * w2.y + v.z * w2.z + v.w * w2.w;
    }
    #pragma unroll
    for (int o = 16; o > 0; o >>= 1) {
        p0 += __shfl_down_sync(0xffffffffu, p0, o);
        p1 += __shfl_down_sync(0xffffffffu, p1, o);
        p2 += __shfl_down_sync(0xffffffffu, p2, o);
    }
    __shared__ float s0[8], s1[8], s2[8];
    int wid = tid >> 5, lid = tid & 31;
    if (lid == 0) { s0[wid] = p0; s1[wid] = p1; s2[wid] = p2; }
    __syncthreads();
    if (tid == 0) {
        float z0 = gate_b[0] + gumbel[b * 3 + 0];
        float z1 = gate_b[1] + gumbel[b * 3 + 1];
        float z2 = gate_b[2] + gumbel[b * 3 + 2];
        #pragma unroll
        for (int w = 0; w < 8; w++) { z0 += s0[w]; z1 += s1[w]; z2 += s2[w]; }
        int am = 0; float zm = z0;
        if (z1 > zm) { am = 1; zm = z1; }
        if (z2 > zm) { am = 2; }
        out_gate[b * 3 + 0] = (am == 0) ? 1.f : 0.f;
        out_gate[b * 3 + 1] = (am == 1) ? 1.f : 0.f;
        out_gate[b * 3 + 2] = (am == 2) ? 1.f : 0.f;
        g_sel[b] = am;
    }
}

// ---------------------------------------------------------------------------
// fp16 mma.sync GEMM core.  C[128,128] per CTA, 8 warps 2x4, warp tile 64x32.
// ---------------------------------------------------------------------------
struct GemmCtx {
    uint32_t sm32;
    int tid, lane, g, tg, wm0, wn0;
};

__device__ __forceinline__ void gemm_init(GemmCtx& cx, void* sm) {
    cx.sm32 = smem_u32(sm);
    cx.tid  = threadIdx.x;
    cx.lane = cx.tid & 31;
    cx.g    = cx.lane >> 2;
    cx.tg   = cx.lane & 3;
    int wid = cx.tid >> 5;
    cx.wm0  = (wid >> 2) * 64;   // 2 warp-rows
    cx.wn0  = (wid & 3) * 32;    // 4 warp-cols
}

// load one BK=64 tile of A (rows m0..+127) and B (rows n0..+127) into stage sl
__device__ __forceinline__ void gemm_load(const GemmCtx& cx,
                                          const __half* __restrict__ A, int m0,
                                          const __half* __restrict__ Bw, int n0,
                                          int kc, int sl) {
    int r0  = cx.tid >> 3;         // 0..31
    int seg = cx.tid & 7;          // 16B segment in row
    uint32_t abase = cx.sm32 + sl * (2 * STAGE_B);
    uint32_t bbase = abase + STAGE_B;
    #pragma unroll
    for (int p = 0; p < 4; p++) {
        int r = r0 + p * 32;
        cp16(abase + r * ROWB + seg * 16, A  + (size_t)(m0 + r) * 2048 + kc + seg * 8);
        cp16(bbase + r * ROWB + seg * 16, Bw + (size_t)(n0 + r) * 2048 + kc + seg * 8);
    }
}

__device__ __forceinline__ void gemm_compute(const GemmCtx& cx, int sl,
                                             float c[4][4][4]) {
    uint32_t As = cx.sm32 + sl * (2 * STAGE_B);
    uint32_t Bs = As + STAGE_B;
    int l = cx.lane;
    int arow = cx.wm0 + (l & 15);
    int aks  = (l >> 4) * 8;
    int brow0 = cx.wn0 + (l & 7) + ((l >> 4) << 3);
    int bks  = ((l >> 3) & 1) * 8;
    #pragma unroll
    for (int kk = 0; kk < BK; kk += 16) {
        uint32_t a[4][4], b[4][2];
        #pragma unroll
        for (int i = 0; i < 4; i++) {
            ldsm_x4(a[i][0], a[i][1], a[i][2], a[i][3],
                    As + (arow + i * 16) * ROWB + (kk + aks) * 2);
        }
        #pragma unroll
        for (int j2 = 0; j2 < 2; j2++) {
            ldsm_x4(b[j2 * 2][0], b[j2 * 2][1], b[j2 * 2 + 1][0], b[j2 * 2 + 1][1],
                    Bs + (brow0 + j2 * 16) * ROWB + (kk + bks) * 2);
        }
        #pragma unroll
        for (int i = 0; i < 4; i++)
            #pragma unroll
            for (int j = 0; j < 4; j++)
                mma_f16(c[i][j], a[i][0], a[i][1], a[i][2], a[i][3],
                        b[j][0], b[j][1]);
    }
}

// Full K-loop GEMM: operands (A0,B0) for tiles [0,split), (A1,B1) after.
__device__ __forceinline__ void gemm_run(const GemmCtx& cx,
                                         const __half* A0, const __half* B0,
                                         const __half* A1, const __half* B1,
                                         int m0, int n0, int NT, int split,
                                         float c[4][4][4])
{
    #pragma unroll
    for (int i = 0; i < 4; i++)
        #pragma unroll
        for (int j = 0; j < 4; j++)
            #pragma unroll
            for (int q = 0; q < 4; q++) c[i][j][q] = 0.f;

    auto tl = [&](int t, int sl) {
        const __half* A; const __half* B; int kc;
        if (t < split) { A = A0; B = B0; kc = t * BK; }
        else           { A = A1; B = B1; kc = (t - split) * BK; }
        gemm_load(cx, A, m0, B, n0, kc, sl);
    };

    tl(0, 0); cp_commit();
    tl(1, 1); cp_commit();

    for (int t = 0; t < NT; t++) {
        cp_wait<NSTAGE - 2>();
        __syncthreads();
        int nt = t + NSTAGE - 1;
        if (nt < NT) tl(nt, nt % NSTAGE);
        cp_commit();
        gemm_compute(cx, t % NSTAGE, c);
    }
    cp_wait<0>();
    __syncthreads();
}

// spin until *p >= tgt (one thread polls, then CTA-wide acquire)
__device__ __forceinline__ void wait_count(volatile unsigned* p, unsigned tgt) {
    if (threadIdx.x == 0) {
        while (*p < tgt) __nanosleep(64);
    }
    __syncthreads();
    __threadfence();
}

// ---------------------------------------------------------------------------
// Kernel 1 (persistent mega): subcell tiles (mb-major) -> fusion -> LN
// ---------------------------------------------------------------------------
__global__ __launch_bounds__(NTHREADS, 2)
void mega_kernel(const float* __restrict__ b_ih,
                 const float* __restrict__ b_hh,
                 const float* __restrict__ fusion_b,
                 const float* __restrict__ prev_master,
                 const float* __restrict__ ln_g,
                 const float* __restrict__ ln_b,
                 float* __restrict__ out_sub,
                 float* __restrict__ out_master)
{
    extern __shared__ char smraw[];
    GemmCtx cx; gemm_init(cx, smraw);
    __shared__ unsigned sw;
    float c[4][4][4];

    for (;;) {
        __syncthreads();
        if (threadIdx.x == 0) sw = atomicAdd(&g_work, 1u);
        __syncthreads();
        unsigned w = sw;
        if (w >= N_TILES) return;

        if (w < N_SUB_TILES) {
            // ---------------- subcell tile (mb-major order) ----------------
            int mb = w / 48;
            int r  = w % 48;
            int s  = r / 16;
            int nb = r % 16;
            int m0 = mb * BM, n0 = nb * BN;

            gemm_run(cx, g_x16, g_wih16 + (size_t)s * HD * ID,
                     g_sub16 + (size_t)s * BSZ * HD,
                     g_whh16 + (size_t)s * HD * HD,
                     m0, n0, 64, 32, c);

            const float* bi = b_ih + (size_t)s * HD;
            const float* bh = b_hh + (size_t)s * HD;
            #pragma unroll
            for (int i = 0; i < 4; i++) {
                int rlo = m0 + cx.wm0 + i * 16 + cx.g;
                int rhi = rlo + 8;
                int selo = g_sel[rlo], sehi = g_sel[rhi];
                float* olo = out_sub + ((size_t)s * BSZ + rlo) * HD;
                float* ohi = out_sub + ((size_t)s * BSZ + rhi) * HD;
                __half* wlo = g_weighted16 + (size_t)rlo * HD;
                __half* whi = g_weighted16 + (size_t)rhi * HD;
                #pragma unroll
                for (int j = 0; j < 4; j++) {
                    int n = n0 + cx.wn0 + j * 8 + cx.tg * 2;
                    float2 bv0 = *(const float2*)(bi + n);
                    float2 bv1 = *(const float2*)(bh + n);
                    float bs0 = bv0.x + bv1.x, bs1 = bv0.y + bv1.y;
                    float2 vlo = make_float2(tanhf(c[i][j][0] + bs0),
                                             tanhf(c[i][j][1] + bs1));
                    float2 vhi = make_float2(tanhf(c[i][j][2] + bs0),
                                             tanhf(c[i][j][3] + bs1));
                    *(float2*)(olo + n) = vlo;
                    *(float2*)(ohi + n) = vhi;
                    if (selo == s) *(__half2*)(wlo + n) = __floats2half2_rn(vlo.x, vlo.y);
                    if (sehi == s) *(__half2*)(whi + n) = __floats2half2_rn(vhi.x, vhi.y);
                }
            }
            __threadfence();
            __syncthreads();
            if (threadIdx.x == 0) atomicAdd(&g_fus_ready[mb], 1u);

        } else if (w < N_SUB_TILES + N_FUS_TILES) {
            // ---------------- fusion tile ----------------
            int f  = w - N_SUB_TILES;
            int mb = f / 16;
            int nb = f % 16;
            int m0 = mb * BM, n0 = nb * BN;

            wait_count(&g_fus_ready[mb], 48u);   // 3 s * 16 nb subcell tiles

            gemm_run(cx, g_weighted16, g_fw16, g_weighted16, g_fw16,
                     m0, n0, 32, 32, c);

            #pragma unroll
            for (int i = 0; i < 4; i++) {
                int rlo = m0 + cx.wm0 + i * 16 + cx.g;
                int rhi = rlo + 8;
                const float* plo = prev_master + (size_t)rlo * HD;
                const float* phi = prev_master + (size_t)rhi * HD;
                float* olo = out_master + (size_t)rlo * HD;
                float* ohi = out_master + (size_t)rhi * HD;
                #pragma unroll
                for (int j = 0; j < 4; j++) {
                    int n = n0 + cx.wn0 + j * 8 + cx.tg * 2;
                    float2 fb = *(const float2*)(fusion_b + n);
                    float2 mlo = *(const float2*)(plo + n);
                    float2 mhi = *(const float2*)(phi + n);
                    float2 vlo = make_float2(c[i][j][0] + fb.x + mlo.x,
                                             c[i][j][1] + fb.y + mlo.y);
                    float2 vhi = make_float2(c[i][j][2] + fb.x + mhi.x,
                                             c[i][j][3] + fb.y + mhi.y);
                    *(float2*)(olo + n) = vlo;
                    *(float2*)(ohi + n) = vhi;
                }
            }
            __threadfence();
            __syncthreads();
            if (threadIdx.x == 0) atomicAdd(&g_ln_ready[mb], 1u);

        } else {
            // -------- LayerNorm + sigmoid tile (8 rows; 1 row per warp) --------
            int idx = w - (N_SUB_TILES + N_FUS_TILES);
            int mb  = idx / 16;
            int grp = idx % 16;
            wait_count(&g_ln_ready[mb], 16u);    // all 16 fusion nb tiles

            int wid = cx.tid >> 5, lid = cx.lane;
            int rowi = mb * 128 + grp * 8 + wid;
            float* row = out_master + (size_t)rowi * HD;
            float sum = 0.f, sq = 0.f;
            #pragma unroll 4
            for (int h = lid * 4; h < HD; h += 128) {
                float4 t = *(const float4*)(row + h);
                sum += t.x + t.y + t.z + t.w;
                sq  += t.x * t.x + t.y * t.y + t.z * t.z + t.w * t.w;
            }
            #pragma unroll
            for (int o = 16; o > 0; o >>= 1) {
                sum += __shfl_xor_sync(0xffffffffu, sum, o);
                sq  += __shfl_xor_sync(0xffffffffu, sq, o);
            }
            float mu   = sum / (float)HD;
            float var  = sq / (float)HD - mu * mu;
            float rstd = rsqrtf(var + LN_EPS);
            #pragma unroll 4
            for (int h = lid * 4; h < HD; h += 128) {
                float4 t = *(const float4*)(row + h);
                float4 gg = *(const float4*)(ln_g + h);
                float4 bb = *(const float4*)(ln_b + h);
                float n0v = (t.x - mu) * rstd * gg.x + bb.x;
                float n1v = (t.y - mu) * rstd * gg.y + bb.y;
                float n2v = (t.z - mu) * rstd * gg.z + bb.z;
                float n3v = (t.w - mu) * rstd * gg.w + bb.w;
                float4 o;
                o.x = 1.f / (1.f + expf(-n0v));
                o.y = 1.f / (1.f + expf(-n1v));
                o.z = 1.f / (1.f + expf(-n2v));
                o.w = 1.f / (1.f + expf(-n3v));
                *(float4*)(row + h) = o;
            }
        }
    }
}

// ---------------------------------------------------------------------------
// Launch
// ---------------------------------------------------------------------------
extern "C" void kernel_launch(void* const* d_in, const int* in_sizes, int n_in,
                              void* d_out, int out_size)
{
    const float* x           = (const float*)d_in[0];   // [B, I]
    const float* prev_master = (const float*)d_in[1];   // [B, H]
    const float* prev_sub    = (const float*)d_in[2];   // [S, B, H]
    const float* gumbel      = (const float*)d_in[3];   // [B, S]
    const float* W_ih        = (const float*)d_in[4];   // [S, H, I]
    const float* W_hh        = (const float*)d_in[5];   // [S, H, H]
    const float* b_ih        = (const float*)d_in[6];   // [S, H]
    const float* b_hh        = (const float*)d_in[7];   // [S, H]
    const float* gate_W      = (const float*)d_in[8];   // [S, H]
    const float* gate_b      = (const float*)d_in[9];   // [S]
    const float* fusion_W    = (const float*)d_in[10];  // [H, H]
    const float* fusion_b    = (const float*)d_in[11];  // [H]
    const float* ln_g        = (const float*)d_in[12];  // [H]
    const float* ln_b        = (const float*)d_in[13];  // [H]

    float* out        = (float*)d_out;
    float* out_master = out;                                  // B*H
    float* out_gate   = out + (size_t)BSZ * HD;               // B*S
    float* out_sub    = out + (size_t)BSZ * HD + BSZ * NS;    // S*B*H

    cudaFuncSetAttribute(mega_kernel,
                         cudaFuncAttributeMaxDynamicSharedMemorySize, SMEM_BYTES);

    prologue_kernel<<<PRO_BLOCKS, 256>>>(x, prev_sub, W_ih, W_hh, fusion_W,
                                         prev_master, gumbel, gate_W, gate_b,
                                         out_gate);

    mega_kernel<<<MEGA_GRID, NTHREADS, SMEM_BYTES>>>(
        b_ih, b_hh, fusion_b, prev_master, ln_g, ln_b, out_sub, out_master);
}